// round 8
// baseline (speedup 1.0000x reference)
#include <cuda_runtime.h>
#include <cuda_bf16.h>
#include <cfloat>
#include <cmath>

#define BB 32
#define NN 256
#define LL 50
#define BN (BB * NN)          // 8192
#define DU 32
#define DI 32
#define DC 16
#define DD 48
#define FEAT 128
#define NCTA 592              // 148 SMs x 4 CTAs: exactly one wave

// ---------------- scratch (no allocs allowed) ----------------
__device__ float g_feat[BN * FEAT];
__device__ float g_logits[BN];
__device__ __align__(16) float g_WbcT[64 * 48];  // [j][k] = w1b - w1c
__device__ __align__(16) float g_WacT[64 * 48];  // [j][k] = w1a + w1c
__device__ __align__(16) float g_WdT [64 * 48];  // [j][k] = w1d
__device__ float g_v[64];                        // w2 @ w3
__device__ float g_cs[1];                        // b2.w3 + b3

// ---------------- helpers ----------------
__device__ __forceinline__ void ffma2(unsigned long long& acc,
                                      unsigned long long a,
                                      unsigned long long b) {
    asm("fma.rn.f32x2 %0, %1, %2, %0;" : "+l"(acc) : "l"(a), "l"(b));
}
__device__ __forceinline__ void upk(unsigned long long v, float& x, float& y) {
    asm("mov.b64 {%0,%1}, %2;" : "=f"(x), "=f"(y) : "l"(v));
}
__device__ __forceinline__ unsigned long long pk(float x, float y) {
    unsigned long long r;
    asm("mov.b64 %0, {%1,%2};" : "=l"(r) : "f"(x), "f"(y));
    return r;
}
__device__ __forceinline__ unsigned sptr(const void* p) {
    return (unsigned)__cvta_generic_to_shared(p);
}
__device__ __forceinline__ void lds_v2u64(unsigned addr,
                                          unsigned long long& a,
                                          unsigned long long& b) {
    asm("ld.shared.v2.u64 {%0,%1}, [%2];" : "=l"(a), "=l"(b) : "r"(addr));
}
__device__ __forceinline__ void sts_u64(unsigned addr, unsigned long long v) {
    asm("st.shared.u64 [%0], %1;" :: "r"(addr), "l"(v));
}
__device__ __forceinline__ void cpasync16(unsigned dst, const void* src) {
    asm volatile("cp.async.ca.shared.global [%0], [%1], 16;"
                 :: "r"(dst), "l"(src));
}
__device__ __forceinline__ void cpasync8(unsigned dst, const void* src) {
    asm volatile("cp.async.ca.shared.global [%0], [%1], 8;"
                 :: "r"(dst), "l"(src));
}
__device__ __forceinline__ void cpasync_commit() {
    asm volatile("cp.async.commit_group;" ::: "memory");
}
__device__ __forceinline__ void cpasync_wait0() {
    asm volatile("cp.async.wait_group 0;" ::: "memory");
}

// ---------------- K0: fold attention weights ----------------
__global__ void setup_kernel(const float* __restrict__ w1,
                             const float* __restrict__ w2,
                             const float* __restrict__ w3,
                             const float* __restrict__ b2,
                             const float* __restrict__ b3)
{
    int e = blockIdx.x * 256 + threadIdx.x;
    if (blockIdx.x < 12) {
        int j = e / 48, k = e % 48;
        float a = w1[k * 64 + j];
        float b = w1[(48 + k) * 64 + j];
        float c = w1[(96 + k) * 64 + j];
        float d = w1[(144 + k) * 64 + j];
        g_WbcT[j * 48 + k] = b - c;
        g_WacT[j * 48 + k] = a + c;
        g_WdT [j * 48 + k] = d;
    } else {
        int t = threadIdx.x;
        if (t < 64) {
            float v = 0.f;
#pragma unroll
            for (int m = 0; m < 16; m++) v += w2[t * 16 + m] * w3[m];
            g_v[t] = v;
        } else if (t == 64) {
            float cs = b3[0];
#pragma unroll
            for (int m = 0; m < 16; m++) cs += b2[m] * w3[m];
            g_cs[0] = cs;
        }
    }
}

// ---------------- K1: persistent pipelined attention ----------------
__global__ void __launch_bounds__(128, 4) attn_kernel(
    const float* __restrict__ emb_user,
    const float* __restrict__ emb_item,
    const float* __restrict__ emb_cate,
    const float* __restrict__ b1,
    const int* __restrict__ user,
    const int* __restrict__ items,
    const int* __restrict__ items_cate,
    const int* __restrict__ ii,
    const int* __restrict__ iic)
{
    const int t     = threadIdx.x;
    const int w     = t >> 5;
    const int lane  = t & 31;
    const int jq    = lane & 15;
    const int khalf = lane >> 4;

    __shared__ __align__(16) unsigned long long Mx[24 * 64];  // [kp][j]
    __shared__ __align__(16) float he_s[2][LL][52];
    __shared__ __align__(16) float q_s[2][48];
    __shared__ __align__(16) float u_s[2][32];
    __shared__ __align__(16) int   idxi_s[4][52];             // ii rows
    __shared__ __align__(16) int   idxc_s[4][52];             // iic rows
    __shared__ float cn_part[2][64];
    __shared__ float v_s[64];
    __shared__ float S[LL][17];
    __shared__ float sc_s[LL];

    const int bn0 = blockIdx.x;
    const int cnt = (BN - 1 - bn0) / NCTA + 1;
    auto bnc = [&](int i) {
        int b = bn0 + i * NCTA;
        return (b < BN) ? b : (BN - 1);
    };

    if (t < 64) v_s[t] = g_v[t];
    const float csv = g_cs[0];

    // per-thread prefetch regs (roles: 64..75 q ids, 96..103 user id)
    int it_n1 = 0, ic_n1 = 0, uid_n1 = 0;

    // ---------- prologue ----------
    // G_pre0: idx(0) -> slot0, idx(1) -> slot1 (8B chunks)
    if (t < 50) {
        int c = (t < 25) ? t : (t - 25);
        if (t < 25) {
            cpasync8(sptr(&idxi_s[0][0]) + c * 8, ii  + (size_t)bnc(0) * LL + c * 2);
            cpasync8(sptr(&idxi_s[1][0]) + c * 8, ii  + (size_t)bnc(1) * LL + c * 2);
        } else {
            cpasync8(sptr(&idxc_s[0][0]) + c * 8, iic + (size_t)bnc(0) * LL + c * 2);
            cpasync8(sptr(&idxc_s[1][0]) + c * 8, iic + (size_t)bnc(1) * LL + c * 2);
        }
    }
    cpasync_commit();
    // prefetch scalar ids for bn_1 (used when issuing G_0)
    if (t >= 64 && t < 76) {
        it_n1 = __ldg(&items[bnc(1)]);
        ic_n1 = __ldg(&items_cate[bnc(1)]);
    }
    if (t >= 96 && t < 104) uid_n1 = __ldg(&user[bnc(1)]);
    cpasync_wait0();
    __syncthreads();

    // G_pre1: he(0) via slot0, q(0)/u(0) direct, idx(2)->slot2
    {
        const unsigned heb = sptr(&he_s[0][0][0]);
#pragma unroll
        for (int u = 0; u < 5; u++) {
            int ch = t + u * 128;
            if (ch < LL * 12) {
                int row = ch / 12, c = ch % 12;
                const float* src;
                unsigned dst;
                if (c < 8) {
                    src = emb_item + (size_t)idxi_s[0][row] * DI + c * 4;
                    dst = heb + row * 208 + c * 16;
                } else {
                    src = emb_cate + (size_t)idxc_s[0][row] * DC + (c - 8) * 4;
                    dst = heb + row * 208 + 128 + (c - 8) * 16;
                }
                cpasync16(dst, src);
            }
        }
        if (t >= 64 && t < 76) {
            int c = t - 64;
            int it0 = __ldg(&items[bnc(0)]);
            int ic0 = __ldg(&items_cate[bnc(0)]);
            const float* src = (c < 8)
                ? emb_item + (size_t)it0 * DI + c * 4
                : emb_cate + (size_t)ic0 * DC + (c - 8) * 4;
            cpasync16(sptr(&q_s[0][0]) + c * 16, src);
        }
        if (t >= 96 && t < 104) {
            int c = t - 96;
            int u0 = __ldg(&user[bnc(0)]);
            cpasync16(sptr(&u_s[0][0]) + c * 16,
                      emb_user + (size_t)u0 * DU + c * 4);
        }
        if (t < 50) {
            if (t < 25)
                cpasync8(sptr(&idxi_s[2][0]) + t * 8,
                         ii + (size_t)bnc(2) * LL + t * 2);
            else
                cpasync8(sptr(&idxc_s[2][0]) + (t - 25) * 8,
                         iic + (size_t)bnc(2) * LL + (t - 25) * 2);
        }
        cpasync_commit();
    }

    // ---------- main loop ----------
    for (int i = 0; i < cnt; i++) {
        const int bn   = bn0 + i * NCTA;
        const int buf  = i & 1;
        const int bufp = (i + 1) & 1;
        const int slp  = (i + 1) & 3;   // idx slot for addressing he(i+1)
        const int sl3  = (i + 3) & 3;   // idx slot being filled
        const int slm  = i & 3;         // idx slot for this bn's mask

        cpasync_wait0();                 // G_{i-1}: he(i), q(i), u(i), idx(i+2)
        __syncthreads();

        // ---- issue G_i: he(i+1), q(i+1), u(i+1), idx(i+3) ----
        {
            const unsigned heb = sptr(&he_s[bufp][0][0]);
#pragma unroll
            for (int u = 0; u < 5; u++) {
                int ch = t + u * 128;
                if (ch < LL * 12) {
                    int row = ch / 12, c = ch % 12;
                    const float* src;
                    unsigned dst;
                    if (c < 8) {
                        src = emb_item + (size_t)idxi_s[slp][row] * DI + c * 4;
                        dst = heb + row * 208 + c * 16;
                    } else {
                        src = emb_cate + (size_t)idxc_s[slp][row] * DC + (c - 8) * 4;
                        dst = heb + row * 208 + 128 + (c - 8) * 16;
                    }
                    cpasync16(dst, src);
                }
            }
            if (t >= 64 && t < 76) {
                int c = t - 64;
                const float* src = (c < 8)
                    ? emb_item + (size_t)it_n1 * DI + c * 4
                    : emb_cate + (size_t)ic_n1 * DC + (c - 8) * 4;
                cpasync16(sptr(&q_s[bufp][0]) + c * 16, src);
            }
            if (t >= 96 && t < 104) {
                int c = t - 96;
                cpasync16(sptr(&u_s[bufp][0]) + c * 16,
                          emb_user + (size_t)uid_n1 * DU + c * 4);
            }
            if (t < 50) {
                if (t < 25)
                    cpasync8(sptr(&idxi_s[sl3][0]) + t * 8,
                             ii + (size_t)bnc(i + 3) * LL + t * 2);
                else
                    cpasync8(sptr(&idxc_s[sl3][0]) + (t - 25) * 8,
                             iic + (size_t)bnc(i + 3) * LL + (t - 25) * 2);
            }
            cpasync_commit();
            // refresh scalar-id prefetch for i+2
            if (t >= 64 && t < 76) {
                it_n1 = __ldg(&items[bnc(i + 2)]);
                ic_n1 = __ldg(&items_cate[bnc(i + 2)]);
            }
            if (t >= 96 && t < 104) uid_n1 = __ldg(&user[bnc(i + 2)]);
        }

        // ---- fold: M[j][k] = Wbc + q[k]*Wd ; cn ----
        {
            const int j = t & 63;
            const int half = t >> 6;
            float cn = (half == 0) ? b1[j] : 0.f;
            const float4* wbc = (const float4*)(g_WbcT + j * 48) + half * 6;
            const float4* wac = (const float4*)(g_WacT + j * 48) + half * 6;
            const float4* wd  = (const float4*)(g_WdT  + j * 48) + half * 6;
            const float4* q4  = (const float4*)&q_s[buf][0] + half * 6;
            unsigned mxb = sptr(Mx) + j * 8 + half * 12 * 512;
#pragma unroll
            for (int c = 0; c < 6; c++) {
                float4 qb = q4[c];
                float4 fb = wbc[c], fa = wac[c], fd = wd[c];
                float mx = fmaf(qb.x, fd.x, fb.x);
                float my = fmaf(qb.y, fd.y, fb.y);
                float mz = fmaf(qb.z, fd.z, fb.z);
                float mw = fmaf(qb.w, fd.w, fb.w);
                sts_u64(mxb + (2 * c) * 512, pk(mx, my));
                sts_u64(mxb + (2 * c + 1) * 512, pk(mz, mw));
                cn = fmaf(qb.x, fa.x, cn);
                cn = fmaf(qb.y, fa.y, cn);
                cn = fmaf(qb.z, fa.z, cn);
                cn = fmaf(qb.w, fa.w, cn);
            }
            cn_part[half][j] = cn;
        }
        __syncthreads();

        // ---- score: A-tile 4 cols x 24 k in regs ----
        {
            unsigned long long A0[12], A1[12], A2[12], A3[12];
            unsigned mb = sptr(Mx) + (4 * jq) * 8 + khalf * 12 * 512;
#pragma unroll
            for (int x = 0; x < 12; x++) {
                lds_v2u64(mb + x * 512,      A0[x], A1[x]);
                lds_v2u64(mb + x * 512 + 16, A2[x], A3[x]);
            }
            const float cn0 = cn_part[0][4 * jq]     + cn_part[1][4 * jq];
            const float cn1 = cn_part[0][4 * jq + 1] + cn_part[1][4 * jq + 1];
            const float cn2 = cn_part[0][4 * jq + 2] + cn_part[1][4 * jq + 2];
            const float cn3 = cn_part[0][4 * jq + 3] + cn_part[1][4 * jq + 3];
            const float v0 = v_s[4 * jq],     v1 = v_s[4 * jq + 1];
            const float v2 = v_s[4 * jq + 2], v3 = v_s[4 * jq + 3];

            const int l0  = (w < 2) ? w * 13 : 26 + (w - 2) * 12;
            const int lc  = (w < 2) ? 13 : 12;
            for (int li = 0; li < lc; li++) {
                const int l = l0 + li;
                unsigned hb = sptr(&he_s[buf][l][0]) + khalf * 96;
                unsigned long long a0 = 0ull, a1 = 0ull, a2 = 0ull, a3 = 0ull;
#pragma unroll
                for (int c = 0; c < 6; c++) {
                    unsigned long long h0, h1;
                    lds_v2u64(hb + c * 16, h0, h1);
                    ffma2(a0, h0, A0[2 * c]);
                    ffma2(a0, h1, A0[2 * c + 1]);
                    ffma2(a1, h0, A1[2 * c]);
                    ffma2(a1, h1, A1[2 * c + 1]);
                    ffma2(a2, h0, A2[2 * c]);
                    ffma2(a2, h1, A2[2 * c + 1]);
                    ffma2(a3, h0, A3[2 * c]);
                    ffma2(a3, h1, A3[2 * c + 1]);
                }
                float x, y;
                upk(a0, x, y); float p0 = x + y;
                upk(a1, x, y); float p1 = x + y;
                upk(a2, x, y); float p2 = x + y;
                upk(a3, x, y); float p3 = x + y;
                p0 += __shfl_xor_sync(0xffffffffu, p0, 16);
                p1 += __shfl_xor_sync(0xffffffffu, p1, 16);
                p2 += __shfl_xor_sync(0xffffffffu, p2, 16);
                p3 += __shfl_xor_sync(0xffffffffu, p3, 16);
                float s;
                s = fmaxf(p0 + cn0, 0.f) * v0;
                s = fmaf(fmaxf(p1 + cn1, 0.f), v1, s);
                s = fmaf(fmaxf(p2 + cn2, 0.f), v2, s);
                s = fmaf(fmaxf(p3 + cn3, 0.f), v3, s);
                S[l][jq] = s;
            }
        }
        __syncthreads();

        // ---- reduce (mask from idx slot i&3) ----
        if (t < LL) {
            float s = csv;
#pragma unroll
            for (int k = 0; k < 16; k++) s += S[t][k];
            sc_s[t] = (idxi_s[slm][t] == 0) ? 0.f : s;
        }
        __syncthreads();

        // ---- pooled + feat ----
        float* fo = g_feat + (size_t)bn * FEAT;
        if (t < 48) {
            float pooled = 0.f;
#pragma unroll 10
            for (int l = 0; l < LL; l++)
                pooled = fmaf(sc_s[l], he_s[buf][l][t], pooled);
            fo[t]      = q_s[buf][t];
            fo[48 + t] = pooled;
        } else if (t < 80) {
            fo[96 + (t - 48)] = u_s[buf][t - 48];
        }
        // next-iteration top wait+sync protects all buffer overwrites
    }
}

// ---------------- K2: FC MLP, balanced register tile ----------------
#define ROWS 16
__global__ void __launch_bounds__(256) fc_kernel(
    const float* __restrict__ fw1, const float* __restrict__ fb1,
    const float* __restrict__ fw2, const float* __restrict__ fb2,
    const float* __restrict__ fw3, const float* __restrict__ fb3)
{
    const int t = threadIdx.x;
    const int row0 = blockIdx.x * ROWS;

    __shared__ __align__(16) float fs[ROWS][132];
    __shared__ __align__(16) float x1[ROWS][204];
    __shared__ __align__(16) float x2[ROWS][84];

    const float4* src = (const float4*)(g_feat + row0 * FEAT);
    for (int i = t; i < ROWS * FEAT / 4; i += 256) {
        float4 v = src[i];
        int r = i >> 5, c = (i & 31) * 4;
        fs[r][c] = v.x; fs[r][c + 1] = v.y;
        fs[r][c + 2] = v.z; fs[r][c + 3] = v.w;
    }
    __syncthreads();

    if (t < 200) {
        const int jjq = t % 50;
        const int rg  = (t / 50) * 4;
        const float* wbase = fw1 + 4 * jjq;
        const unsigned long long b0 = pk(fb1[4 * jjq],     fb1[4 * jjq + 1]);
        const unsigned long long b1v = pk(fb1[4 * jjq + 2], fb1[4 * jjq + 3]);
        unsigned long long acc[4][2];
#pragma unroll
        for (int r = 0; r < 4; r++) { acc[r][0] = b0; acc[r][1] = b1v; }
#pragma unroll 4
        for (int i = 0; i < FEAT; i++) {
            float4 wv = __ldg((const float4*)(wbase + i * 200));
            unsigned long long wp0 = pk(wv.x, wv.y);
            unsigned long long wp1 = pk(wv.z, wv.w);
#pragma unroll
            for (int r = 0; r < 4; r++) {
                float xv = fs[rg + r][i];
                unsigned long long xx = pk(xv, xv);
                ffma2(acc[r][0], xx, wp0);
                ffma2(acc[r][1], xx, wp1);
            }
        }
#pragma unroll
        for (int r = 0; r < 4; r++) {
            float h0, h1, h2, h3;
            upk(acc[r][0], h0, h1);
            upk(acc[r][1], h2, h3);
            float4 o;
            o.x = fmaxf(h0, 0.f); o.y = fmaxf(h1, 0.f);
            o.z = fmaxf(h2, 0.f); o.w = fmaxf(h3, 0.f);
            *(float4*)&x1[rg + r][4 * jjq] = o;
        }
    }
    __syncthreads();

    if (t < 160) {
        const int jjq = t % 20;
        const int rg  = (t / 20) * 2;
        const float* wbase = fw2 + 4 * jjq;
        const unsigned long long b0 = pk(fb2[4 * jjq],     fb2[4 * jjq + 1]);
        const unsigned long long b1v = pk(fb2[4 * jjq + 2], fb2[4 * jjq + 3]);
        unsigned long long acc[2][2];
#pragma unroll
        for (int r = 0; r < 2; r++) { acc[r][0] = b0; acc[r][1] = b1v; }
#pragma unroll 4
        for (int i = 0; i < 200; i++) {
            float4 wv = __ldg((const float4*)(wbase + i * 80));
            unsigned long long wp0 = pk(wv.x, wv.y);
            unsigned long long wp1 = pk(wv.z, wv.w);
#pragma unroll
            for (int r = 0; r < 2; r++) {
                float xv = x1[rg + r][i];
                unsigned long long xx = pk(xv, xv);
                ffma2(acc[r][0], xx, wp0);
                ffma2(acc[r][1], xx, wp1);
            }
        }
#pragma unroll
        for (int r = 0; r < 2; r++) {
            float h0, h1, h2, h3;
            upk(acc[r][0], h0, h1);
            upk(acc[r][1], h2, h3);
            float4 o;
            o.x = fmaxf(h0, 0.f); o.y = fmaxf(h1, 0.f);
            o.z = fmaxf(h2, 0.f); o.w = fmaxf(h3, 0.f);
            *(float4*)&x2[rg + r][4 * jjq] = o;
        }
    }
    __syncthreads();

    if (t < ROWS) {
        const unsigned long long* wp = (const unsigned long long*)fw3;
        const unsigned long long* xp = (const unsigned long long*)&x2[t][0];
        unsigned long long acc = 0ull;
#pragma unroll
        for (int ip = 0; ip < 40; ip++)
            ffma2(acc, xp[ip], __ldg(&wp[ip]));
        float a, b;
        upk(acc, a, b);
        float s = a + b + fb3[0];
        g_logits[row0 + t] = 1.0f / (1.0f + expf(-s));
    }
}

// ---------------- K3: masked softmax ----------------
__global__ void __launch_bounds__(256) softmax_kernel(
    const int* __restrict__ items, float* __restrict__ out)
{
    const int b = blockIdx.x;
    const int t = threadIdx.x;
    const int wid = t >> 5, lane = t & 31;

    __shared__ float red[8];
    __shared__ float s_mx, s_sum;

    float l = g_logits[b * NN + t];
    bool masked = (items[b * NN + t] == 0);
    float val = masked ? -FLT_MAX : l;

    float mx = val;
#pragma unroll
    for (int o = 16; o > 0; o >>= 1)
        mx = fmaxf(mx, __shfl_down_sync(0xffffffffu, mx, o));
    if (lane == 0) red[wid] = mx;
    __syncthreads();
    if (t == 0) {
        float m = red[0];
#pragma unroll
        for (int w = 1; w < 8; w++) m = fmaxf(m, red[w]);
        s_mx = m;
    }
    __syncthreads();
    float m = s_mx;

    float e = masked ? 0.0f : expf(l - m);
    float sum = e;
#pragma unroll
    for (int o = 16; o > 0; o >>= 1)
        sum += __shfl_down_sync(0xffffffffu, sum, o);
    if (lane == 0) red[wid] = sum;
    __syncthreads();
    if (t == 0) {
        float s = 0.0f;
#pragma unroll
        for (int w = 0; w < 8; w++) s += red[w];
        s_sum = s;
    }
    __syncthreads();

    out[b * NN + t] = e / s_sum;
}

// ---------------- launch ----------------
extern "C" void kernel_launch(void* const* d_in, const int* in_sizes, int n_in,
                              void* d_out, int out_size)
{
    const float* emb_user  = (const float*)d_in[0];
    const float* emb_item  = (const float*)d_in[1];
    const float* emb_cate  = (const float*)d_in[2];
    const float* att_w1    = (const float*)d_in[3];
    const float* att_b1    = (const float*)d_in[4];
    const float* att_w2    = (const float*)d_in[5];
    const float* att_b2    = (const float*)d_in[6];
    const float* att_w3    = (const float*)d_in[7];
    const float* att_b3    = (const float*)d_in[8];
    const float* fc_w1     = (const float*)d_in[9];
    const float* fc_b1     = (const float*)d_in[10];
    const float* fc_w2     = (const float*)d_in[11];
    const float* fc_b2     = (const float*)d_in[12];
    const float* fc_w3     = (const float*)d_in[13];
    const float* fc_b3     = (const float*)d_in[14];
    const int*   user      = (const int*)d_in[15];
    const int*   items     = (const int*)d_in[16];
    const int*   items_cate= (const int*)d_in[17];
    const int*   ii        = (const int*)d_in[18];
    const int*   iic       = (const int*)d_in[19];
    float* out = (float*)d_out;

    setup_kernel<<<13, 256>>>(att_w1, att_w2, att_w3, att_b2, att_b3);
    attn_kernel<<<NCTA, 128>>>(emb_user, emb_item, emb_cate, att_b1,
                               user, items, items_cate, ii, iic);
    fc_kernel<<<BN / ROWS, 256>>>(fc_w1, fc_b1, fc_w2, fc_b2, fc_w3, fc_b3);
    softmax_kernel<<<BB, 256>>>(items, out);
}